// round 3
// baseline (speedup 1.0000x reference)
#include <cuda_runtime.h>
#include <math.h>

// ---------------- constants ----------------
#define BATCH 64
#define T_IN 1000
#define C_IN 4
#define F_CH 320
#define KW 26
#define POOL 13
#define T_CONV 975
#define T_POOL 75
#define H_GRU 320
#define H3 960
#define FLAT 48000
#define D1 2000
#define D2 301

#define CONV_M (BATCH * T_CONV)       // 62400
#define CONV_K (KW * C_IN)            // 104
#define PROJ_M (BATCH * T_POOL)       // 4800
#define SPLITK1 16
#define KCH1 3008
#define SPLITK2 8
#define KCH2 256

// ---------------- packed f32x2 helpers (sm_100+; FFMA2 in SASS) ----------------
__device__ __forceinline__ unsigned long long f2pk(float lo, float hi) {
    unsigned long long r;
    asm("mov.b64 %0, {%1, %2};" : "=l"(r) : "f"(lo), "f"(hi));
    return r;
}
__device__ __forceinline__ void f2upk(unsigned long long v, float& lo, float& hi) {
    asm("mov.b64 {%0, %1}, %2;" : "=f"(lo), "=f"(hi) : "l"(v));
}
__device__ __forceinline__ unsigned long long ffma2(
    unsigned long long a, unsigned long long b, unsigned long long c) {
    unsigned long long d;
    asm("fma.rn.f32x2 %0, %1, %2, %3;" : "=l"(d) : "l"(a), "l"(b), "l"(c));
    return d;
}

// ---------------- scratch (device globals; no allocation allowed) ----------------
__device__ float g_conv[CONV_M * F_CH];                 // 79.9 MB
__device__ float g_pool[PROJ_M * F_CH];                 // 6.1 MB
__device__ float g_mx[PROJ_M * 2 * H3];                 // 36.9 MB  [(b*75+t)*1920 + dir*960 + col]
__device__ float g_y[BATCH * T_POOL * 2 * H_GRU];       // 12.3 MB  [(b*75+t)*640 + dir*320 + col]
__device__ float g_h[2][2][BATCH * H_GRU];              // [dir][parity]
__device__ float g_fc1_part[SPLITK1][BATCH * D1];
__device__ float g_h1[BATCH * D1];
__device__ float g_fc2_part[SPLITK2][BATCH * D2];

// ---------------- generic tiled SGEMM: C = A(MxK) * B(KxN) ----------------
// tile 64(M) x 128(N) x 16(K), 256 threads, 4x8 micro-tile (accumulated as 4x4 f32x2 pairs).
// amode==1: A row r maps to the conv-window view of in[]: off = (r/975)*4000 + (r%975)*4,
//           element j at A[off + j] (free im2col: window is contiguous with row stride 4).
// gridDim.z = split-K chunks, each writes C + z*zstride. bias/act applied only when gridDim.z==1.
__global__ void __launch_bounds__(256) sgemm_kernel(
    const float* __restrict__ A, int lda, int amode,
    const float* __restrict__ B, int ldb,
    float* __restrict__ C, int ldc, long zstride,
    int M, int N, int K, int kchunk,
    const float* __restrict__ bias, int act)
{
    __shared__ float As[16][68];
    __shared__ float Bs[16][132];

    const int tid = threadIdx.x;
    const int ntile = blockIdx.x, mtile = blockIdx.y, z = blockIdx.z;
    const int k0 = z * kchunk;
    const int kend = min(k0 + kchunk, K);
    float* Cz = C + (long)z * zstride;

    // A-load pattern: k = tid&15 (const), rows m = tid/16 + j*16
    const int a_k = tid & 15;
    long a_off[4];
#pragma unroll
    for (int j = 0; j < 4; j++) {
        int r = mtile * 64 + (tid >> 4) + j * 16;   // M always a multiple of 64 here
        a_off[j] = amode ? ((long)(r / 975) * 4000 + (long)(r % 975) * 4)
                         : (long)r * lda;
    }
    // B-load pattern: n = tid&127 (const), rows k = tid/128 + j*2
    const int b_n = tid & 127;
    const int n_glob_b = ntile * 128 + b_n;
    const bool b_ok = (n_glob_b < N);

    const int m0 = (tid >> 4) * 4;
    const int n0 = (tid & 15) * 8;

    // acc2[i][p] holds columns (n0+2p, n0+2p+1) for micro-row i, packed f32x2
    unsigned long long acc2[4][4];
#pragma unroll
    for (int i = 0; i < 4; i++)
#pragma unroll
        for (int p = 0; p < 4; p++) acc2[i][p] = 0ULL;

    for (int kt = k0; kt < kend; kt += 16) {
        // load A tile (64 x 16)
        {
            int kg = kt + a_k;
            bool kok = (kg < kend);
#pragma unroll
            for (int j = 0; j < 4; j++) {
                float v = kok ? A[a_off[j] + kg] : 0.f;
                As[a_k][(tid >> 4) + j * 16] = v;
            }
        }
        // load B tile (16 x 128)
#pragma unroll
        for (int j = 0; j < 8; j++) {
            int kk = (tid >> 7) + j * 2;
            int kg = kt + kk;
            float v = (b_ok && kg < kend) ? B[(long)kg * ldb + n_glob_b] : 0.f;
            Bs[kk][b_n] = v;
        }
        __syncthreads();
#pragma unroll
        for (int kk = 0; kk < 16; kk++) {
            float4 a = *(const float4*)&As[kk][m0];
            // B pairs read as packed 64-bit (8B-aligned: row=132 floats, n0 mult of 8)
            const unsigned long long* bq =
                (const unsigned long long*)&Bs[kk][n0];
            unsigned long long bp0 = bq[0], bp1 = bq[1], bp2 = bq[2], bp3 = bq[3];
            float av[4] = {a.x, a.y, a.z, a.w};
#pragma unroll
            for (int i = 0; i < 4; i++) {
                unsigned long long ai = f2pk(av[i], av[i]);
                acc2[i][0] = ffma2(ai, bp0, acc2[i][0]);
                acc2[i][1] = ffma2(ai, bp1, acc2[i][1]);
                acc2[i][2] = ffma2(ai, bp2, acc2[i][2]);
                acc2[i][3] = ffma2(ai, bp3, acc2[i][3]);
            }
        }
        __syncthreads();
    }

    const bool doepi = (gridDim.z == 1);
#pragma unroll
    for (int i = 0; i < 4; i++) {
        int r = mtile * 64 + m0 + i;
#pragma unroll
        for (int p = 0; p < 4; p++) {
            float v0, v1;
            f2upk(acc2[i][p], v0, v1);
            int col0 = ntile * 128 + n0 + 2 * p;
#pragma unroll
            for (int q = 0; q < 2; q++) {
                int col = col0 + q;
                float v = q ? v1 : v0;
                if (col < N) {
                    if (doepi) {
                        if (bias) v += bias[col];
                        if (act == 1) v = fmaxf(v, 0.f);
                    }
                    Cz[(long)r * ldc + col] = v;
                }
            }
        }
    }
}

// ---------------- maxpool over conv output ----------------
__global__ void pool_kernel()
{
    int i = blockIdx.x * blockDim.x + threadIdx.x;
    if (i >= PROJ_M * F_CH) return;
    int f = i % F_CH;
    int r = i / F_CH;            // b*75 + tp
    int tp = r % T_POOL;
    int b = r / T_POOL;
    long base = ((long)(b * T_CONV + tp * POOL)) * F_CH + f;
    float m = g_conv[base];
#pragma unroll
    for (int p = 1; p < POOL; p++) m = fmaxf(m, g_conv[base + (long)p * F_CH]);
    g_pool[i] = m;
}

// ---------------- GRU ----------------
__global__ void init_h_kernel()
{
    int i = blockIdx.x * blockDim.x + threadIdx.x;
    if (i < BATCH * H_GRU) { g_h[0][0][i] = 0.f; g_h[1][0][i] = 0.f; }
}

// One time step, both directions. 128 blocks: dir = blk>>6, slice = blk&63 (5 h-cols each).
// smem: full h (64 x 321 padded, conflict-free), rk slice (320 x 16: [z0..z4 r0..r4 h0..h4 pad]),
// mi staging (64 x 16). Kernel boundary provides the step synchronization; h is double-buffered.
__global__ void __launch_bounds__(128) gru_step_kernel(
    const float* __restrict__ rk_fw, const float* __restrict__ rk_bw,
    const float* __restrict__ b_fw, const float* __restrict__ b_bw,
    int t)
{
    extern __shared__ float sm[];
    float* sh_h = sm;                     // 64*321
    float* sh_rk = sm + 64 * 321;         // 320*16
    float* sh_mi = sh_rk + 320 * 16;      // 64*16

    const int tid = threadIdx.x;
    const int dir = blockIdx.x >> 6;
    const int slice = blockIdx.x & 63;
    const float* rk = dir ? rk_bw : rk_fw;
    const float* gb = dir ? b_bw : b_fw;
    const float* hin = g_h[dir][t & 1];
    float* hout = g_h[dir][(t + 1) & 1];

    for (int i = tid; i < BATCH * H_GRU; i += 128) {
        int b = i / H_GRU, k = i - b * H_GRU;
        sh_h[b * 321 + k] = hin[i];
    }
    for (int i = tid; i < H_GRU * 16; i += 128) {
        int k = i >> 4, c = i & 15;
        float v = 0.f;
        if (c < 15) {
            int gate = c / 5, jj = c - gate * 5;
            v = rk[(long)k * H3 + gate * H_GRU + slice * 5 + jj];
        }
        sh_rk[i] = v;
    }
    __syncthreads();

    {
        const int b = tid & 63;
        const int cg = tid >> 6;   // 0 or 1 -> cols [0..7] / [8..15]
        unsigned long long acc2[4];
#pragma unroll
        for (int p = 0; p < 4; p++) acc2[p] = 0ULL;
        const float* hrow = &sh_h[b * 321];
#pragma unroll 4
        for (int k = 0; k < H_GRU; k++) {
            float hv = hrow[k];
            unsigned long long hp2 = f2pk(hv, hv);
            // warp-uniform broadcast reads, 8B-aligned (k*64 + cg*32 bytes)
            const unsigned long long* bq =
                (const unsigned long long*)&sh_rk[k * 16 + cg * 8];
            acc2[0] = ffma2(hp2, bq[0], acc2[0]);
            acc2[1] = ffma2(hp2, bq[1], acc2[1]);
            acc2[2] = ffma2(hp2, bq[2], acc2[2]);
            acc2[3] = ffma2(hp2, bq[3], acc2[3]);
        }
        float a0, a1, a2, a3, a4, a5, a6, a7;
        f2upk(acc2[0], a0, a1); f2upk(acc2[1], a2, a3);
        f2upk(acc2[2], a4, a5); f2upk(acc2[3], a6, a7);
        float4* mi4 = (float4*)&sh_mi[b * 16 + cg * 8];
        mi4[0] = make_float4(a0, a1, a2, a3);
        mi4[1] = make_float4(a4, a5, a6, a7);
    }
    __syncthreads();

    const int t_in = dir ? (T_POOL - 1 - t) : t;
    for (int pi = tid; pi < 320; pi += 128) {
        int b = pi / 5, jj = pi - (pi / 5) * 5;
        int col = slice * 5 + jj;
        float miz = sh_mi[b * 16 + jj]      + gb[H3 + col];
        float mir = sh_mi[b * 16 + 5 + jj]  + gb[H3 + H_GRU + col];
        float mih = sh_mi[b * 16 + 10 + jj] + gb[H3 + 2 * H_GRU + col];
        const float* mx = &g_mx[((long)(b * T_POOL + t_in)) * (2 * H3) + dir * H3];
        float zg = 1.f / (1.f + __expf(-(mx[col] + miz)));
        float rg = 1.f / (1.f + __expf(-(mx[H_GRU + col] + mir)));
        float cand = tanhf(mx[2 * H_GRU + col] + rg * mih);
        float hp = sh_h[b * 321 + col];
        float hn = zg * hp + (1.f - zg) * cand;
        hout[b * H_GRU + col] = hn;
        g_y[((long)(b * T_POOL + t_in)) * (2 * H_GRU) + dir * H_GRU + col] = hn;
    }
}

// ---------------- FC reduces (deterministic two-stage split-K) ----------------
__global__ void fc1_reduce_kernel(const float* __restrict__ b1)
{
    int i = blockIdx.x * blockDim.x + threadIdx.x;
    if (i >= BATCH * D1) return;
    float s = 0.f;
#pragma unroll
    for (int z = 0; z < SPLITK1; z++) s += g_fc1_part[z][i];
    s += b1[i % D1];
    g_h1[i] = fmaxf(s, 0.f);
}

__global__ void fc2_reduce_kernel(const float* __restrict__ b2, float* __restrict__ out)
{
    int i = blockIdx.x * blockDim.x + threadIdx.x;
    if (i >= BATCH * D2) return;
    float s = 0.f;
#pragma unroll
    for (int z = 0; z < SPLITK2; z++) s += g_fc2_part[z][i];
    s += b2[i % D2];
    out[i] = 1.f / (1.f + __expf(-s));
}

// ---------------- launch ----------------
extern "C" void kernel_launch(void* const* d_in, const int* in_sizes, int n_in,
                              void* d_out, int out_size)
{
    const float* in    = (const float*)d_in[0];
    const float* convw = (const float*)d_in[1];
    const float* convb = (const float*)d_in[2];
    const float* fwk   = (const float*)d_in[3];
    const float* fwrk  = (const float*)d_in[4];
    const float* fwb   = (const float*)d_in[5];
    const float* bwk   = (const float*)d_in[6];
    const float* bwrk  = (const float*)d_in[7];
    const float* bwb   = (const float*)d_in[8];
    const float* w1    = (const float*)d_in[9];
    const float* b1    = (const float*)d_in[10];
    const float* w2    = (const float*)d_in[11];
    const float* b2    = (const float*)d_in[12];
    float* out = (float*)d_out;

    float *p_conv, *p_pool, *p_mx, *p_y, *p_h1, *p_fc1p, *p_fc2p;
    cudaGetSymbolAddress((void**)&p_conv, g_conv);
    cudaGetSymbolAddress((void**)&p_pool, g_pool);
    cudaGetSymbolAddress((void**)&p_mx,   g_mx);
    cudaGetSymbolAddress((void**)&p_y,    g_y);
    cudaGetSymbolAddress((void**)&p_h1,   g_h1);
    cudaGetSymbolAddress((void**)&p_fc1p, g_fc1_part);
    cudaGetSymbolAddress((void**)&p_fc2p, g_fc2_part);

    const int smem_step = (64 * 321 + 320 * 16 + 64 * 16) * 4;  // 106752 B
    cudaFuncSetAttribute(gru_step_kernel,
                         cudaFuncAttributeMaxDynamicSharedMemorySize, smem_step);

    // 1) conv as GEMM over the stride-4 window view, bias+relu fused
    {
        dim3 grid((F_CH + 127) / 128, CONV_M / 64, 1);
        sgemm_kernel<<<grid, 256>>>(in, 0, 1, convw, F_CH,
                                    p_conv, F_CH, 0,
                                    CONV_M, F_CH, CONV_K, CONV_K, convb, 1);
    }
    // 2) maxpool 13
    pool_kernel<<<(PROJ_M * F_CH + 255) / 256, 256>>>();
    // 3) GRU input projections (fw, bw), input bias fused
    {
        dim3 grid((H3 + 127) / 128, PROJ_M / 64, 1);
        sgemm_kernel<<<grid, 256>>>(p_pool, F_CH, 0, fwk, H3,
                                    p_mx, 2 * H3, 0,
                                    PROJ_M, H3, F_CH, F_CH, fwb, 0);
        sgemm_kernel<<<grid, 256>>>(p_pool, F_CH, 0, bwk, H3,
                                    p_mx + H3, 2 * H3, 0,
                                    PROJ_M, H3, F_CH, F_CH, bwb, 0);
    }
    // 4) GRU recurrence: 75 steps, both directions per launch
    init_h_kernel<<<(BATCH * H_GRU + 255) / 256, 256>>>();
    for (int t = 0; t < T_POOL; t++) {
        gru_step_kernel<<<128, 128, smem_step>>>(fwrk, bwrk, fwb, bwb, t);
    }
    // 5) FC1 split-K (deterministic partials + reduce)
    {
        dim3 grid((D1 + 127) / 128, 1, SPLITK1);
        sgemm_kernel<<<grid, 256>>>(p_y, FLAT, 0, w1, D1,
                                    p_fc1p, D1, (long)BATCH * D1,
                                    BATCH, D1, FLAT, KCH1, nullptr, 0);
    }
    fc1_reduce_kernel<<<(BATCH * D1 + 255) / 256, 256>>>(b1);
    // 6) FC2 split-K
    {
        dim3 grid((D2 + 127) / 128, 1, SPLITK2);
        sgemm_kernel<<<grid, 256>>>(p_h1, D1, 0, w2, D2,
                                    p_fc2p, D2, (long)BATCH * D2,
                                    BATCH, D2, D1, KCH2, nullptr, 0);
    }
    fc2_reduce_kernel<<<(BATCH * D2 + 255) / 256, 256>>>(b2, out);
}

// round 5
// speedup vs baseline: 1.5550x; 1.5550x over previous
#include <cuda_runtime.h>
#include <math.h>
#include <stdint.h>

// ---------------- constants ----------------
#define BATCH 64
#define T_IN 1000
#define C_IN 4
#define F_CH 320
#define KW 26
#define POOL 13
#define T_CONV 975
#define T_POOL 75
#define H_GRU 320
#define H3 960
#define FLAT 48000
#define D1 2000
#define D2 301

#define CONV_M (BATCH * T_CONV)       // 62400
#define CONV_K (KW * C_IN)            // 104
#define PROJ_M (BATCH * T_POOL)       // 4800
#define SPLITK1 32
#define KCH1 1500
#define SPLITK2 8
#define KCH2 256

typedef unsigned long long ull;

// ---------------- packed f32x2 helpers (FFMA2 in SASS) ----------------
__device__ __forceinline__ ull f2pk(float lo, float hi) {
    ull r;
    asm("mov.b64 %0, {%1, %2};" : "=l"(r) : "f"(lo), "f"(hi));
    return r;
}
__device__ __forceinline__ void f2upk(ull v, float& lo, float& hi) {
    asm("mov.b64 {%0, %1}, %2;" : "=f"(lo), "=f"(hi) : "l"(v));
}
__device__ __forceinline__ ull ffma2(ull a, ull b, ull c) {
    ull d;
    asm("fma.rn.f32x2 %0, %1, %2, %3;" : "=l"(d) : "l"(a), "l"(b), "l"(c));
    return d;
}

// ---------------- cp.async helpers ----------------
__device__ __forceinline__ void cp_async4(uint32_t smem_addr, const void* gptr, int src_sz) {
    asm volatile("cp.async.ca.shared.global [%0], [%1], 4, %2;"
                 :: "r"(smem_addr), "l"(gptr), "r"(src_sz) : "memory");
}
__device__ __forceinline__ void cp_commit() {
    asm volatile("cp.async.commit_group;" ::: "memory");
}
__device__ __forceinline__ void cp_wait1() {
    asm volatile("cp.async.wait_group 1;" ::: "memory");
}

// ---------------- scratch (device globals; no allocation allowed) ----------------
__device__ float g_conv[CONV_M * F_CH];                 // 79.9 MB
__device__ float g_pool[PROJ_M * F_CH];                 // 6.1 MB
__device__ float g_mx[PROJ_M * 2 * H3];                 // 36.9 MB
__device__ float g_y[BATCH * T_POOL * 2 * H_GRU];       // 12.3 MB
__device__ float g_h[2][2][BATCH * H_GRU];              // [dir][parity]
__device__ float g_fc1_part[SPLITK1][BATCH * D1];
__device__ float g_h1[BATCH * D1];
__device__ float g_fc2_part[SPLITK2][BATCH * D2];

// ---------------- tiled SGEMM: C = A(MxK) * B(KxN) ----------------
// tile 64(M) x 128(N) x 16(K), 256 threads, 4x8 micro-tile as 4x4 f32x2 pairs.
// Thread s = tid&15 owns column pairs {2s, 2s+32, 2s+64, 2s+96} (conflict-free LDS.64).
// 2-stage cp.async double buffer on the K loop.
// amode==1: A row r -> conv-window view: off = (r/975)*4000 + (r%975)*4 (free im2col).
// gridDim.z = split-K chunks -> C + z*zstride. bias/act only when gridDim.z==1.
__global__ void __launch_bounds__(256) sgemm_kernel(
    const float* __restrict__ A, int lda, int amode,
    const float* __restrict__ B, int ldb,
    float* __restrict__ C, int ldc, long zstride,
    int M, int N, int K, int kchunk,
    const float* __restrict__ bias, int act)
{
    __shared__ __align__(16) float As[2][16][68];
    __shared__ __align__(16) float Bs[2][16][132];

    const int tid = threadIdx.x;
    const int ntile = blockIdx.x, mtile = blockIdx.y, z = blockIdx.z;
    const int k0 = z * kchunk;
    const int kend = min(k0 + kchunk, K);
    float* Cz = C + (long)z * zstride;

    // A-load pattern: k = tid&15 (const), rows m = tid/16 + j*16
    const int a_k = tid & 15;
    long a_off[4];
#pragma unroll
    for (int j = 0; j < 4; j++) {
        int r = mtile * 64 + (tid >> 4) + j * 16;   // M always a multiple of 64
        a_off[j] = amode ? ((long)(r / 975) * 4000 + (long)(r % 975) * 4)
                         : (long)r * lda;
    }
    // B-load pattern: n = tid&127 (const), rows k = tid/128 + j*2
    const int b_n = tid & 127;
    const int n_glob_b = ntile * 128 + b_n;
    const bool b_ok = (n_glob_b < N);

    const int m0 = (tid >> 4) * 4;
    const int s  = tid & 15;           // column-pair owner

    const uint32_t as_base = (uint32_t)__cvta_generic_to_shared(&As[0][0][0]);
    const uint32_t bs_base = (uint32_t)__cvta_generic_to_shared(&Bs[0][0][0]);
    const uint32_t asz = 16 * 68 * 4, bsz = 16 * 132 * 4;

    ull acc2[4][4];
#pragma unroll
    for (int i = 0; i < 4; i++)
#pragma unroll
        for (int p = 0; p < 4; p++) acc2[i][p] = 0ULL;

    const int nt = (kend - k0 + 15) >> 4;

    // tile loader (cp.async, zero-fill out-of-range)
    auto load_tile = [&](int kt, int buf) {
        int kgA = kt + a_k;
        int szA = (kgA < kend) ? 4 : 0;
        uint32_t ab = as_base + buf * asz + (uint32_t)(a_k * 68 + (tid >> 4)) * 4;
#pragma unroll
        for (int j = 0; j < 4; j++)
            cp_async4(ab + j * 16 * 4, A + a_off[j] + kgA, szA);
#pragma unroll
        for (int j = 0; j < 8; j++) {
            int kk = (tid >> 7) + j * 2;
            int kg = kt + kk;
            int sz = (b_ok && kg < kend) ? 4 : 0;
            cp_async4(bs_base + buf * bsz + (uint32_t)(kk * 132 + b_n) * 4,
                      B + (long)kg * ldb + n_glob_b, sz);
        }
        cp_commit();
    };

    load_tile(k0, 0);
    for (int ti = 0; ti < nt; ti++) {
        if (ti + 1 < nt) load_tile(k0 + (ti + 1) * 16, (ti + 1) & 1);
        else cp_commit();               // empty group keeps accounting uniform
        cp_wait1();
        __syncthreads();
        const int buf = ti & 1;
#pragma unroll
        for (int kk = 0; kk < 16; kk++) {
            float4 a = *(const float4*)&As[buf][kk][m0];
            const ull* brow = (const ull*)&Bs[buf][kk][0];
            ull bp0 = brow[s];          // cols 2s,2s+1
            ull bp1 = brow[s + 16];     // cols 2s+32,..
            ull bp2 = brow[s + 32];     // cols 2s+64,..
            ull bp3 = brow[s + 48];     // cols 2s+96,..
            float av[4] = {a.x, a.y, a.z, a.w};
#pragma unroll
            for (int i = 0; i < 4; i++) {
                ull ai = f2pk(av[i], av[i]);
                acc2[i][0] = ffma2(ai, bp0, acc2[i][0]);
                acc2[i][1] = ffma2(ai, bp1, acc2[i][1]);
                acc2[i][2] = ffma2(ai, bp2, acc2[i][2]);
                acc2[i][3] = ffma2(ai, bp3, acc2[i][3]);
            }
        }
        __syncthreads();
    }

    const bool doepi = (gridDim.z == 1);
#pragma unroll
    for (int i = 0; i < 4; i++) {
        int r = mtile * 64 + m0 + i;
#pragma unroll
        for (int p = 0; p < 4; p++) {
            float v0, v1;
            f2upk(acc2[i][p], v0, v1);
            int col0 = ntile * 128 + 2 * s + 32 * p;
#pragma unroll
            for (int q = 0; q < 2; q++) {
                int col = col0 + q;
                float v = q ? v1 : v0;
                if (col < N) {
                    if (doepi) {
                        if (bias) v += bias[col];
                        if (act == 1) v = fmaxf(v, 0.f);
                    }
                    Cz[(long)r * ldc + col] = v;
                }
            }
        }
    }
}

// ---------------- maxpool over conv output ----------------
__global__ void pool_kernel()
{
    int i = blockIdx.x * blockDim.x + threadIdx.x;
    if (i >= PROJ_M * F_CH) return;
    int f = i % F_CH;
    int r = i / F_CH;            // b*75 + tp
    int tp = r % T_POOL;
    int b = r / T_POOL;
    long base = ((long)(b * T_CONV + tp * POOL)) * F_CH + f;
    float m = g_conv[base];
#pragma unroll
    for (int p = 1; p < POOL; p++) m = fmaxf(m, g_conv[base + (long)p * F_CH]);
    g_pool[i] = m;
}

// ---------------- GRU ----------------
__global__ void init_h_kernel()
{
    int i = blockIdx.x * blockDim.x + threadIdx.x;
    if (i < BATCH * H_GRU) { g_h[0][0][i] = 0.f; g_h[1][0][i] = 0.f; }
}

// One time step, both directions. 128 blocks x 256 threads (2 warps/SMSP).
// dir = blk>>6, slice = blk&63 (5 h-cols each). k-loop split in halves across tid>>7,
// partials combined through smem. h: 64x321 padded (conflict-free), rk slice 320x16.
#define SMEM_STEP ((64 * 321 + 320 * 16 + 2 * 64 * 16) * 4)
__global__ void __launch_bounds__(256) gru_step_kernel(
    const float* __restrict__ rk_fw, const float* __restrict__ rk_bw,
    const float* __restrict__ b_fw, const float* __restrict__ b_bw,
    int t)
{
    extern __shared__ float sm[];
    float* sh_h  = sm;                      // 64*321
    float* sh_rk = sm + 64 * 321;           // 320*16
    float* sh_mi = sh_rk + 320 * 16;        // 2*64*16

    const int tid = threadIdx.x;
    const int dir = blockIdx.x >> 6;
    const int slice = blockIdx.x & 63;
    const float* rk = dir ? rk_bw : rk_fw;
    const float* gb = dir ? b_bw : b_fw;
    const float* hin = g_h[dir][t & 1];
    float* hout = g_h[dir][(t + 1) & 1];

    // vectorized h load: 5120 floats = 1280 float4
    {
        const float4* hin4 = (const float4*)hin;
        for (int i = tid; i < 64 * 80; i += 256) {
            float4 v = hin4[i];
            int b = i / 80, k = (i - b * 80) * 4;
            float* d = &sh_h[b * 321 + k];
            d[0] = v.x; d[1] = v.y; d[2] = v.z; d[3] = v.w;
        }
    }
    for (int i = tid; i < H_GRU * 16; i += 256) {
        int k = i >> 4, c = i & 15;
        float v = 0.f;
        if (c < 15) {
            int gate = c / 5, jj = c - gate * 5;
            v = rk[(long)k * H3 + gate * H_GRU + slice * 5 + jj];
        }
        sh_rk[i] = v;
    }
    __syncthreads();

    {
        const int b  = tid & 63;
        const int cg = (tid >> 6) & 1;      // cols [0..7] / [8..15]
        const int kh = tid >> 7;            // k-half
        ull acc2[4] = {0ULL, 0ULL, 0ULL, 0ULL};
        const float* hrow = &sh_h[b * 321 + kh * 160];
        const float* rkp  = &sh_rk[kh * 160 * 16 + cg * 8];
#pragma unroll 4
        for (int k = 0; k < 160; k++) {
            float hv = hrow[k];
            ull hp2 = f2pk(hv, hv);
            const ull* bq = (const ull*)(rkp + k * 16);
            acc2[0] = ffma2(hp2, bq[0], acc2[0]);
            acc2[1] = ffma2(hp2, bq[1], acc2[1]);
            acc2[2] = ffma2(hp2, bq[2], acc2[2]);
            acc2[3] = ffma2(hp2, bq[3], acc2[3]);
        }
        float a0, a1, a2, a3, a4, a5, a6, a7;
        f2upk(acc2[0], a0, a1); f2upk(acc2[1], a2, a3);
        f2upk(acc2[2], a4, a5); f2upk(acc2[3], a6, a7);
        float4* mi4 = (float4*)&sh_mi[kh * 1024 + b * 16 + cg * 8];
        mi4[0] = make_float4(a0, a1, a2, a3);
        mi4[1] = make_float4(a4, a5, a6, a7);
    }
    __syncthreads();

    const int t_in = dir ? (T_POOL - 1 - t) : t;
    for (int pi = tid; pi < 320; pi += 256) {
        int b = pi / 5, jj = pi - (pi / 5) * 5;
        int col = slice * 5 + jj;
        float miz = sh_mi[b * 16 + jj]      + sh_mi[1024 + b * 16 + jj]      + gb[H3 + col];
        float mir = sh_mi[b * 16 + 5 + jj]  + sh_mi[1024 + b * 16 + 5 + jj]  + gb[H3 + H_GRU + col];
        float mih = sh_mi[b * 16 + 10 + jj] + sh_mi[1024 + b * 16 + 10 + jj] + gb[H3 + 2 * H_GRU + col];
        const float* mx = &g_mx[((long)(b * T_POOL + t_in)) * (2 * H3) + dir * H3];
        float zg = 1.f / (1.f + __expf(-(mx[col] + miz)));
        float rg = 1.f / (1.f + __expf(-(mx[H_GRU + col] + mir)));
        float cx = mx[2 * H_GRU + col] + rg * mih;
        float e2 = __expf(2.f * cx);
        float cand = 1.f - 2.f / (e2 + 1.f);          // tanh(cx)
        float hp = sh_h[b * 321 + col];
        float hn = zg * hp + (1.f - zg) * cand;
        hout[b * H_GRU + col] = hn;
        g_y[((long)(b * T_POOL + t_in)) * (2 * H_GRU) + dir * H_GRU + col] = hn;
    }
}

// ---------------- FC reduces (deterministic two-stage split-K) ----------------
__global__ void fc1_reduce_kernel(const float* __restrict__ b1)
{
    int i = blockIdx.x * blockDim.x + threadIdx.x;
    if (i >= BATCH * D1) return;
    float s = 0.f;
#pragma unroll
    for (int z = 0; z < SPLITK1; z++) s += g_fc1_part[z][i];
    s += b1[i % D1];
    g_h1[i] = fmaxf(s, 0.f);
}

__global__ void fc2_reduce_kernel(const float* __restrict__ b2, float* __restrict__ out)
{
    int i = blockIdx.x * blockDim.x + threadIdx.x;
    if (i >= BATCH * D2) return;
    float s = 0.f;
#pragma unroll
    for (int z = 0; z < SPLITK2; z++) s += g_fc2_part[z][i];
    s += b2[i % D2];
    out[i] = 1.f / (1.f + __expf(-s));
}

// ---------------- launch ----------------
extern "C" void kernel_launch(void* const* d_in, const int* in_sizes, int n_in,
                              void* d_out, int out_size)
{
    const float* in    = (const float*)d_in[0];
    const float* convw = (const float*)d_in[1];
    const float* convb = (const float*)d_in[2];
    const float* fwk   = (const float*)d_in[3];
    const float* fwrk  = (const float*)d_in[4];
    const float* fwb   = (const float*)d_in[5];
    const float* bwk   = (const float*)d_in[6];
    const float* bwrk  = (const float*)d_in[7];
    const float* bwb   = (const float*)d_in[8];
    const float* w1    = (const float*)d_in[9];
    const float* b1    = (const float*)d_in[10];
    const float* w2    = (const float*)d_in[11];
    const float* b2    = (const float*)d_in[12];
    float* out = (float*)d_out;

    float *p_conv, *p_pool, *p_mx, *p_y, *p_h1, *p_fc1p, *p_fc2p;
    cudaGetSymbolAddress((void**)&p_conv, g_conv);
    cudaGetSymbolAddress((void**)&p_pool, g_pool);
    cudaGetSymbolAddress((void**)&p_mx,   g_mx);
    cudaGetSymbolAddress((void**)&p_y,    g_y);
    cudaGetSymbolAddress((void**)&p_h1,   g_h1);
    cudaGetSymbolAddress((void**)&p_fc1p, g_fc1_part);
    cudaGetSymbolAddress((void**)&p_fc2p, g_fc2_part);

    cudaFuncSetAttribute(gru_step_kernel,
                         cudaFuncAttributeMaxDynamicSharedMemorySize, SMEM_STEP);

    // 1) conv as GEMM over the stride-4 window view, bias+relu fused
    {
        dim3 grid((F_CH + 127) / 128, CONV_M / 64, 1);
        sgemm_kernel<<<grid, 256>>>(in, 0, 1, convw, F_CH,
                                    p_conv, F_CH, 0,
                                    CONV_M, F_CH, CONV_K, CONV_K, convb, 1);
    }
    // 2) maxpool 13
    pool_kernel<<<(PROJ_M * F_CH + 255) / 256, 256>>>();
    // 3) GRU input projections (fw, bw), input bias fused
    {
        dim3 grid((H3 + 127) / 128, PROJ_M / 64, 1);
        sgemm_kernel<<<grid, 256>>>(p_pool, F_CH, 0, fwk, H3,
                                    p_mx, 2 * H3, 0,
                                    PROJ_M, H3, F_CH, F_CH, fwb, 0);
        sgemm_kernel<<<grid, 256>>>(p_pool, F_CH, 0, bwk, H3,
                                    p_mx + H3, 2 * H3, 0,
                                    PROJ_M, H3, F_CH, F_CH, bwb, 0);
    }
    // 4) GRU recurrence: 75 steps, both directions per launch
    init_h_kernel<<<(BATCH * H_GRU + 255) / 256, 256>>>();
    for (int t = 0; t < T_POOL; t++) {
        gru_step_kernel<<<128, 256, SMEM_STEP>>>(fwrk, bwrk, fwb, bwb, t);
    }
    // 5) FC1 split-K (deterministic partials + reduce)
    {
        dim3 grid((D1 + 127) / 128, 1, SPLITK1);
        sgemm_kernel<<<grid, 256>>>(p_y, FLAT, 0, w1, D1,
                                    p_fc1p, D1, (long)BATCH * D1,
                                    BATCH, D1, FLAT, KCH1, nullptr, 0);
    }
    fc1_reduce_kernel<<<(BATCH * D1 + 255) / 256, 256>>>(b1);
    // 6) FC2 split-K
    {
        dim3 grid((D2 + 127) / 128, 1, SPLITK2);
        sgemm_kernel<<<grid, 256>>>(p_h1, D1, 0, w2, D2,
                                    p_fc2p, D2, (long)BATCH * D2,
                                    BATCH, D2, D1, KCH2, nullptr, 0);
    }
    fc2_reduce_kernel<<<(BATCH * D2 + 255) / 256, 256>>>(b2, out);
}